// round 8
// baseline (speedup 1.0000x reference)
#include <cuda_runtime.h>
#include <math.h>
#include <stdint.h>

#define H    1024
#define F    2816
#define E    8
#define NTOK 2048
#define MAXK 2

#define BM 128
#define BN 64
#define BK 32

// ---------------- device scratch (static, no allocation) ----------------
__device__ int   g_count[E];
__device__ int   g_offs[E];
__device__ int   g_tok[E * NTOK];
__device__ float g_wt [E * NTOK];
__device__ float g_act[(size_t)MAXK * NTOK * F];       // tf32-rounded silu activations
__device__ float g_x32 [(size_t)NTOK * H];             // tf32-rounded x
__device__ float g_w132[(size_t)E * F * H];            // tf32-rounded w1
__device__ float g_w232[(size_t)E * H * F];            // tf32-rounded w2

// ---------------- helpers ----------------
__device__ __forceinline__ float to_tf32(float x) {
    float r; asm("cvt.rna.tf32.f32 %0, %1;" : "=f"(r) : "f"(x)); return r;
}
__device__ __forceinline__ uint32_t smem_u32(const void* p) {
    uint32_t a;
    asm("{ .reg .u64 t; cvta.to.shared.u64 t, %1; cvt.u32.u64 %0, t; }" : "=r"(a) : "l"(p));
    return a;
}

#define CP_A16(dst, src, n) asm volatile("cp.async.cg.shared.global [%0], [%1], 16, %2;" :: "r"(dst), "l"(src), "r"(n))
#define CP_COMMIT()         asm volatile("cp.async.commit_group;" ::: "memory")
#define CP_WAIT1()          asm volatile("cp.async.wait_group 1;" ::: "memory")
#define CP_WAIT0()          asm volatile("cp.async.wait_group 0;" ::: "memory")

#define MMA_TF32(c, a, b)                                                        \
    asm volatile("mma.sync.aligned.m16n8k8.row.col.f32.tf32.tf32.f32 "           \
        "{%0,%1,%2,%3}, {%4,%5,%6,%7}, {%8,%9}, {%0,%1,%2,%3};"                  \
        : "+f"((c)[0]), "+f"((c)[1]), "+f"((c)[2]), "+f"((c)[3])                 \
        : "r"((a)[0]), "r"((a)[1]), "r"((a)[2]), "r"((a)[3]),                    \
          "r"((b)[0]), "r"((b)[1]))

// ---------------- tiny kernels ----------------
__global__ void zero_counts_kernel() { if (threadIdx.x < E) g_count[threadIdx.x] = 0; }

__global__ void offs_kernel() {
    if (threadIdx.x == 0) {
        int o = 0;
        for (int e = 0; e < E; e++) { g_offs[e] = o; o += g_count[e]; }
    }
}

// ---------------- tf32 pre-convert kernels (dst = device symbols) ----------------
__global__ __launch_bounds__(256) void cvt_x_kernel(const float* __restrict__ src) {
    const size_t i = (size_t)blockIdx.x * 256 + threadIdx.x;
    float4 v = ((const float4*)src)[i];
    v.x = to_tf32(v.x); v.y = to_tf32(v.y); v.z = to_tf32(v.z); v.w = to_tf32(v.w);
    ((float4*)g_x32)[i] = v;
}
__global__ __launch_bounds__(256) void cvt_w1_kernel(const float* __restrict__ src) {
    const size_t i = (size_t)blockIdx.x * 256 + threadIdx.x;
    float4 v = ((const float4*)src)[i];
    v.x = to_tf32(v.x); v.y = to_tf32(v.y); v.z = to_tf32(v.z); v.w = to_tf32(v.w);
    ((float4*)g_w132)[i] = v;
}
__global__ __launch_bounds__(256) void cvt_w2_kernel(const float* __restrict__ src) {
    const size_t i = (size_t)blockIdx.x * 256 + threadIdx.x;
    float4 v = ((const float4*)src)[i];
    v.x = to_tf32(v.x); v.y = to_tf32(v.y); v.z = to_tf32(v.z); v.w = to_tf32(v.w);
    ((float4*)g_w232)[i] = v;
}

// ---------------- router ----------------
__global__ __launch_bounds__(256) void router_kernel(const float* __restrict__ x,
                                                     const float* __restrict__ gw,
                                                     const int* __restrict__ topk_ptr) {
    const int token = blockIdx.x;
    const float* xr = x + (size_t)token * H;
    float p[E];
#pragma unroll
    for (int e = 0; e < E; e++) p[e] = 0.f;
    for (int h = threadIdx.x; h < H; h += blockDim.x) {
        const float xv = xr[h];
#pragma unroll
        for (int e = 0; e < E; e++) p[e] += xv * gw[e * H + h];
    }
#pragma unroll
    for (int e = 0; e < E; e++)
#pragma unroll
        for (int o = 16; o > 0; o >>= 1) p[e] += __shfl_xor_sync(0xffffffffu, p[e], o);

    __shared__ float sp[8][E];
    const int warp = threadIdx.x >> 5, lane = threadIdx.x & 31;
    if (lane == 0)
#pragma unroll
        for (int e = 0; e < E; e++) sp[warp][e] = p[e];
    __syncthreads();

    if (threadIdx.x == 0) {
        float lg[E];
#pragma unroll
        for (int e = 0; e < E; e++) {
            float s = 0.f;
            for (int w = 0; w < 8; w++) s += sp[w][e];
            lg[e] = s;
        }
        float mx = lg[0];
#pragma unroll
        for (int e = 1; e < E; e++) mx = fmaxf(mx, lg[e]);
        float pr[E], psum = 0.f;
#pragma unroll
        for (int e = 0; e < E; e++) { pr[e] = expf(lg[e] - mx); psum += pr[e]; }
#pragma unroll
        for (int e = 0; e < E; e++) pr[e] /= psum;

        int k = topk_ptr[0];
        if (k < 1) k = 1;
        if (k > MAXK) k = MAXK;

        bool used[E];
#pragma unroll
        for (int e = 0; e < E; e++) used[e] = false;
        int sel[MAXK]; float sw[MAXK]; float ssum = 0.f;
        for (int j = 0; j < k; j++) {
            int best = -1; float bv = -1.f;
            for (int e = 0; e < E; e++)
                if (!used[e] && pr[e] > bv) { bv = pr[e]; best = e; }
            used[best] = true; sel[j] = best; sw[j] = bv; ssum += bv;
        }
        const float inv = 1.f / ssum;
        for (int j = 0; j < k; j++) {
            const int ee = sel[j];
            const int pos = atomicAdd(&g_count[ee], 1);
            g_tok[ee * NTOK + pos] = token;
            g_wt [ee * NTOK + pos] = sw[j] * inv;
        }
    }
}

// ---------------- tf32 mma.sync grouped GEMM, cp.async double-buffered ----------------
// D[128x64] per CTA = A[128xK] @ B_e[64xK]^T ; 128 threads, 4 warps (2M x 2N),
// warp tile 64x32. All inputs pre-rounded to tf32 values.
// Smem layout: 32-float rows, 16B chunks XOR-swizzled by (row&7) -> conflict-free LDS.
template <bool IS_UP, int K, int NB>
__global__ __launch_bounds__(128, 4) void mma_gemm_kernel(float* __restrict__ out) {
    const int e   = blockIdx.z;
    const int cnt = g_count[e];
    const int m0  = blockIdx.y * BM;
    if (m0 >= cnt) return;
    const int n0   = blockIdx.x * BN;
    const int base = g_offs[e];

    __shared__ float sA[2][BM][BK];   // 32 KB
    __shared__ float sB[2][BN][BK];   // 16 KB

    const int tid  = threadIdx.x;
    const int lane = tid & 31;
    const int warp = tid >> 5;
    const int wm   = warp & 1;       // 0..1
    const int wn   = warp >> 1;      // 0..1
    const int g    = lane >> 2;      // 0..7
    const int t    = lane & 3;       // 0..3

    // ---- staging pointers: thread tid owns A row tid; B row tid>>1 (half tid&1)
    const float* Asrc = IS_UP ? g_x32 : g_act;
    const float* Bsrc = IS_UP ? g_w132 : g_w232;

    const int am = m0 + tid;
    const bool aval = am < cnt;
    const float* aptr;
    if (IS_UP) aptr = aval ? Asrc + (size_t)g_tok[e * NTOK + am] * K : Asrc;
    else       aptr = aval ? Asrc + (size_t)(base + am) * K : Asrc;
    const float* bptr = Bsrc + (size_t)e * NB * K + (size_t)(n0 + (tid >> 1)) * K;

    // swizzled smem dst addresses (u32)
    const uint32_t sA0 = smem_u32(&sA[0][0][0]);
    const uint32_t sB0 = smem_u32(&sB[0][0][0]);
    uint32_t dstA[8], dstB[4];
#pragma unroll
    for (int ch = 0; ch < 8; ch++)
        dstA[ch] = sA0 + (uint32_t)tid * (BK * 4) + (uint32_t)((ch ^ (tid & 7)) * 16);
#pragma unroll
    for (int j = 0; j < 4; j++) {
        const int ch = (tid & 1) * 4 + j;
        dstB[j] = sB0 + (uint32_t)(tid >> 1) * (BK * 4) + (uint32_t)((ch ^ ((tid >> 1) & 7)) * 16);
    }
    const uint32_t abuf = BM * BK * 4;   // bytes per A stage
    const uint32_t bbuf = BN * BK * 4;

    const int asz = aval ? 16 : 0;

    // ---- accumulators
    float acc[4][4][4];
#pragma unroll
    for (int i = 0; i < 4; i++)
#pragma unroll
        for (int j = 0; j < 4; j++)
#pragma unroll
            for (int c = 0; c < 4; c++) acc[i][j][c] = 0.f;

    const int NS = K / BK;

    // prologue: stage slab 0 -> buf 0
    {
        const float* as = aptr;
        const float* bs = bptr;
#pragma unroll
        for (int ch = 0; ch < 8; ch++) CP_A16(dstA[ch], as + ch * 4, asz);
#pragma unroll
        for (int j = 0; j < 4; j++) {
            const int ch = (tid & 1) * 4 + j;
            CP_A16(dstB[j], bs + ch * 4, 16);
        }
        CP_COMMIT();
    }

    for (int s = 0; s < NS; s++) {
        if (s + 1 < NS) {
            const uint32_t bo = ((s + 1) & 1);
            const float* as = aptr + (s + 1) * BK;
            const float* bs = bptr + (s + 1) * BK;
#pragma unroll
            for (int ch = 0; ch < 8; ch++) CP_A16(dstA[ch] + bo * abuf, as + ch * 4, asz);
#pragma unroll
            for (int j = 0; j < 4; j++) {
                const int ch = (tid & 1) * 4 + j;
                CP_A16(dstB[j] + bo * bbuf, bs + ch * 4, 16);
            }
            CP_COMMIT();
            CP_WAIT1();
        } else {
            CP_WAIT0();
        }
        __syncthreads();

        const int cb = s & 1;
#pragma unroll
        for (int kk = 0; kk < 4; kk++) {
            const int idx0 = ((2 * kk)     ^ g) * 4 + t;   // col index for k-low half
            const int idx1 = ((2 * kk + 1) ^ g) * 4 + t;   // col index for k-high half
            uint32_t a[4][4], b[4][2];
#pragma unroll
            for (int mi = 0; mi < 4; mi++) {
                const int ar = wm * 64 + mi * 16 + g;
                a[mi][0] = __float_as_uint(sA[cb][ar    ][idx0]);
                a[mi][1] = __float_as_uint(sA[cb][ar + 8][idx0]);
                a[mi][2] = __float_as_uint(sA[cb][ar    ][idx1]);
                a[mi][3] = __float_as_uint(sA[cb][ar + 8][idx1]);
            }
#pragma unroll
            for (int nj = 0; nj < 4; nj++) {
                const int bn = wn * 32 + nj * 8 + g;
                b[nj][0] = __float_as_uint(sB[cb][bn][idx0]);
                b[nj][1] = __float_as_uint(sB[cb][bn][idx1]);
            }
#pragma unroll
            for (int mi = 0; mi < 4; mi++)
#pragma unroll
                for (int nj = 0; nj < 4; nj++)
                    MMA_TF32(acc[mi][nj], a[mi], b[nj]);
        }
        __syncthreads();
    }

    // ---- epilogue
#pragma unroll
    for (int mi = 0; mi < 4; mi++) {
        const int r0 = m0 + wm * 64 + mi * 16 + g;
#pragma unroll
        for (int hf = 0; hf < 2; hf++) {
            const int m = r0 + hf * 8;
            if (m < cnt) {
                if (IS_UP) {
                    float* dstrow = g_act + (size_t)(base + m) * F;
#pragma unroll
                    for (int nj = 0; nj < 4; nj++) {
                        const int c = n0 + wn * 32 + nj * 8 + 2 * t;
                        const float v0 = acc[mi][nj][hf * 2];
                        const float v1 = acc[mi][nj][hf * 2 + 1];
                        float2 r;
                        r.x = to_tf32(v0 / (1.f + expf(-v0)));   // pre-rounded for down GEMM
                        r.y = to_tf32(v1 / (1.f + expf(-v1)));
                        *(float2*)(dstrow + c) = r;
                    }
                } else {
                    const int   tok = g_tok[e * NTOK + m];
                    const float wt  = g_wt [e * NTOK + m];
                    float* dstrow = out + (size_t)tok * H;
#pragma unroll
                    for (int nj = 0; nj < 4; nj++) {
                        const int c = n0 + wn * 32 + nj * 8 + 2 * t;
                        atomicAdd(dstrow + c,     acc[mi][nj][hf * 2]     * wt);
                        atomicAdd(dstrow + c + 1, acc[mi][nj][hf * 2 + 1] * wt);
                    }
                }
            }
        }
    }
}

// ---------------- launch ----------------
extern "C" void kernel_launch(void* const* d_in, const int* in_sizes, int n_in,
                              void* d_out, int out_size) {
    const float* x  = (const float*)d_in[0];
    const float* gw = (const float*)d_in[1];
    const float* w1 = (const float*)d_in[2];
    const float* w2 = (const float*)d_in[3];
    const int*   tk = (const int*)d_in[4];
    float* out = (float*)d_out;

    cudaMemsetAsync(out, 0, (size_t)out_size * sizeof(float));
    zero_counts_kernel<<<1, 32>>>();
    router_kernel<<<NTOK, 256>>>(x, gw, tk);
    offs_kernel<<<1, 32>>>();

    cvt_x_kernel <<<(NTOK * H)    / 1024, 256>>>(x);
    cvt_w1_kernel<<<(E * F * H)   / 1024, 256>>>(w1);
    cvt_w2_kernel<<<(E * H * F)   / 1024, 256>>>(w2);

    dim3 gup(F / BN, NTOK / BM, E);
    mma_gemm_kernel<true,  H, F><<<gup, 128>>>(nullptr);

    dim3 gdn(H / BN, NTOK / BM, E);
    mma_gemm_kernel<false, F, H><<<gdn, 128>>>(out);
}

// round 9
// speedup vs baseline: 1.0728x; 1.0728x over previous
#include <cuda_runtime.h>
#include <math.h>
#include <stdint.h>

#define H    1024
#define F    2816
#define E    8
#define NTOK 2048
#define MAXK 2

#define BM 128
#define BN 64
#define BK 32

// ---------------- device scratch (static, no allocation) ----------------
__device__ int   g_count[E];
__device__ int   g_offs[E];
__device__ int   g_tok[E * NTOK];
__device__ float g_wt [E * NTOK];
__device__ float g_act[(size_t)MAXK * NTOK * F];       // tf32-rounded silu activations
__device__ float g_x32 [(size_t)NTOK * H];             // tf32-rounded x

// ---------------- helpers ----------------
__device__ __forceinline__ float to_tf32(float x) {
    float r; asm("cvt.rna.tf32.f32 %0, %1;" : "=f"(r) : "f"(x)); return r;
}
__device__ __forceinline__ uint32_t cvt_frag(float x) {
    float r; asm("cvt.rna.tf32.f32 %0, %1;" : "=f"(r) : "f"(x));
    return __float_as_uint(r);
}
__device__ __forceinline__ uint32_t smem_u32(const void* p) {
    uint32_t a;
    asm("{ .reg .u64 t; cvta.to.shared.u64 t, %1; cvt.u32.u64 %0, t; }" : "=r"(a) : "l"(p));
    return a;
}

#define CP_A16(dst, src, n) asm volatile("cp.async.cg.shared.global [%0], [%1], 16, %2;" :: "r"(dst), "l"(src), "r"(n))
#define CP_COMMIT()         asm volatile("cp.async.commit_group;" ::: "memory")
#define CP_WAIT1()          asm volatile("cp.async.wait_group 1;" ::: "memory")
#define CP_WAIT0()          asm volatile("cp.async.wait_group 0;" ::: "memory")

#define MMA_TF32(c, a, b)                                                        \
    asm volatile("mma.sync.aligned.m16n8k8.row.col.f32.tf32.tf32.f32 "           \
        "{%0,%1,%2,%3}, {%4,%5,%6,%7}, {%8,%9}, {%0,%1,%2,%3};"                  \
        : "+f"((c)[0]), "+f"((c)[1]), "+f"((c)[2]), "+f"((c)[3])                 \
        : "r"((a)[0]), "r"((a)[1]), "r"((a)[2]), "r"((a)[3]),                    \
          "r"((b)[0]), "r"((b)[1]))

// ---------------- tiny kernels ----------------
__global__ void zero_counts_kernel() { if (threadIdx.x < E) g_count[threadIdx.x] = 0; }

__global__ void offs_kernel() {
    if (threadIdx.x == 0) {
        int o = 0;
        for (int e = 0; e < E; e++) { g_offs[e] = o; o += g_count[e]; }
    }
}

// x pre-round (cheap: 16 MB; weights are rounded in-GEMM on fragments)
__global__ __launch_bounds__(256) void cvt_x_kernel(const float* __restrict__ src) {
    const size_t i = (size_t)blockIdx.x * 256 + threadIdx.x;
    float4 v = ((const float4*)src)[i];
    v.x = to_tf32(v.x); v.y = to_tf32(v.y); v.z = to_tf32(v.z); v.w = to_tf32(v.w);
    ((float4*)g_x32)[i] = v;
}

// ---------------- router ----------------
__global__ __launch_bounds__(256) void router_kernel(const float* __restrict__ x,
                                                     const float* __restrict__ gw,
                                                     const int* __restrict__ topk_ptr) {
    const int token = blockIdx.x;
    const float* xr = x + (size_t)token * H;
    float p[E];
#pragma unroll
    for (int e = 0; e < E; e++) p[e] = 0.f;
    for (int h = threadIdx.x; h < H; h += blockDim.x) {
        const float xv = xr[h];
#pragma unroll
        for (int e = 0; e < E; e++) p[e] += xv * gw[e * H + h];
    }
#pragma unroll
    for (int e = 0; e < E; e++)
#pragma unroll
        for (int o = 16; o > 0; o >>= 1) p[e] += __shfl_xor_sync(0xffffffffu, p[e], o);

    __shared__ float sp[8][E];
    const int warp = threadIdx.x >> 5, lane = threadIdx.x & 31;
    if (lane == 0)
#pragma unroll
        for (int e = 0; e < E; e++) sp[warp][e] = p[e];
    __syncthreads();

    if (threadIdx.x == 0) {
        float lg[E];
#pragma unroll
        for (int e = 0; e < E; e++) {
            float s = 0.f;
            for (int w = 0; w < 8; w++) s += sp[w][e];
            lg[e] = s;
        }
        float mx = lg[0];
#pragma unroll
        for (int e = 1; e < E; e++) mx = fmaxf(mx, lg[e]);
        float pr[E], psum = 0.f;
#pragma unroll
        for (int e = 0; e < E; e++) { pr[e] = expf(lg[e] - mx); psum += pr[e]; }
#pragma unroll
        for (int e = 0; e < E; e++) pr[e] /= psum;

        int k = topk_ptr[0];
        if (k < 1) k = 1;
        if (k > MAXK) k = MAXK;

        bool used[E];
#pragma unroll
        for (int e = 0; e < E; e++) used[e] = false;
        int sel[MAXK]; float sw[MAXK]; float ssum = 0.f;
        for (int j = 0; j < k; j++) {
            int best = -1; float bv = -1.f;
            for (int e = 0; e < E; e++)
                if (!used[e] && pr[e] > bv) { bv = pr[e]; best = e; }
            used[best] = true; sel[j] = best; sw[j] = bv; ssum += bv;
        }
        const float inv = 1.f / ssum;
        for (int j = 0; j < k; j++) {
            const int ee = sel[j];
            const int pos = atomicAdd(&g_count[ee], 1);
            g_tok[ee * NTOK + pos] = token;
            g_wt [ee * NTOK + pos] = sw[j] * inv;
        }
    }
}

// ---------------- tf32 mma.sync grouped GEMM, cp.async double-buffered ----------------
// D[128x64] per CTA = A[128xK] @ B_e[64xK]^T ; 128 threads, 4 warps (2M x 2N),
// warp tile 64x32. A pre-rounded (g_x32 / g_act); B raw weights, rounded on
// fragments after LDS (32 cvt/slab vs 64 MMA -> negligible).
template <bool IS_UP, int K, int NB>
__global__ __launch_bounds__(128, 4) void mma_gemm_kernel(const float* __restrict__ Bsrc,
                                                          float* __restrict__ out) {
    const int e   = blockIdx.z;
    const int cnt = g_count[e];
    const int m0  = blockIdx.y * BM;
    if (m0 >= cnt) return;
    const int n0   = blockIdx.x * BN;
    const int base = g_offs[e];

    __shared__ float sA[2][BM][BK];   // 32 KB
    __shared__ float sB[2][BN][BK];   // 16 KB

    const int tid  = threadIdx.x;
    const int lane = tid & 31;
    const int warp = tid >> 5;
    const int wm   = warp & 1;       // 0..1
    const int wn   = warp >> 1;      // 0..1
    const int g    = lane >> 2;      // 0..7
    const int t    = lane & 3;       // 0..3

    const float* Asrc = IS_UP ? g_x32 : g_act;

    const int am = m0 + tid;
    const bool aval = am < cnt;
    const float* aptr;
    if (IS_UP) aptr = aval ? Asrc + (size_t)g_tok[e * NTOK + am] * K : Asrc;
    else       aptr = aval ? Asrc + (size_t)(base + am) * K : Asrc;
    const float* bptr = Bsrc + (size_t)e * NB * K + (size_t)(n0 + (tid >> 1)) * K;

    const uint32_t sA0 = smem_u32(&sA[0][0][0]);
    const uint32_t sB0 = smem_u32(&sB[0][0][0]);
    uint32_t dstA[8], dstB[4];
#pragma unroll
    for (int ch = 0; ch < 8; ch++)
        dstA[ch] = sA0 + (uint32_t)tid * (BK * 4) + (uint32_t)((ch ^ (tid & 7)) * 16);
#pragma unroll
    for (int j = 0; j < 4; j++) {
        const int ch = (tid & 1) * 4 + j;
        dstB[j] = sB0 + (uint32_t)(tid >> 1) * (BK * 4) + (uint32_t)((ch ^ ((tid >> 1) & 7)) * 16);
    }
    const uint32_t abuf = BM * BK * 4;
    const uint32_t bbuf = BN * BK * 4;
    const int asz = aval ? 16 : 0;

    float acc[4][4][4];
#pragma unroll
    for (int i = 0; i < 4; i++)
#pragma unroll
        for (int j = 0; j < 4; j++)
#pragma unroll
            for (int c = 0; c < 4; c++) acc[i][j][c] = 0.f;

    const int NS = K / BK;

    // prologue: stage slab 0 -> buf 0
    {
#pragma unroll
        for (int ch = 0; ch < 8; ch++) CP_A16(dstA[ch], aptr + ch * 4, asz);
#pragma unroll
        for (int j = 0; j < 4; j++) {
            const int ch = (tid & 1) * 4 + j;
            CP_A16(dstB[j], bptr + ch * 4, 16);
        }
        CP_COMMIT();
    }

    for (int s = 0; s < NS; s++) {
        if (s + 1 < NS) {
            const uint32_t bo = ((s + 1) & 1);
            const float* as = aptr + (s + 1) * BK;
            const float* bs = bptr + (s + 1) * BK;
#pragma unroll
            for (int ch = 0; ch < 8; ch++) CP_A16(dstA[ch] + bo * abuf, as + ch * 4, asz);
#pragma unroll
            for (int j = 0; j < 4; j++) {
                const int ch = (tid & 1) * 4 + j;
                CP_A16(dstB[j] + bo * bbuf, bs + ch * 4, 16);
            }
            CP_COMMIT();
            CP_WAIT1();
        } else {
            CP_WAIT0();
        }
        __syncthreads();

        const int cb = s & 1;
#pragma unroll
        for (int kk = 0; kk < 4; kk++) {
            const int idx0 = ((2 * kk)     ^ g) * 4 + t;
            const int idx1 = ((2 * kk + 1) ^ g) * 4 + t;
            uint32_t a[4][4], b[4][2];
#pragma unroll
            for (int mi = 0; mi < 4; mi++) {
                const int ar = wm * 64 + mi * 16 + g;
                a[mi][0] = __float_as_uint(sA[cb][ar    ][idx0]);
                a[mi][1] = __float_as_uint(sA[cb][ar + 8][idx0]);
                a[mi][2] = __float_as_uint(sA[cb][ar    ][idx1]);
                a[mi][3] = __float_as_uint(sA[cb][ar + 8][idx1]);
            }
#pragma unroll
            for (int nj = 0; nj < 4; nj++) {
                const int bn = wn * 32 + nj * 8 + g;
                b[nj][0] = cvt_frag(sB[cb][bn][idx0]);   // round raw weight to tf32
                b[nj][1] = cvt_frag(sB[cb][bn][idx1]);
            }
#pragma unroll
            for (int mi = 0; mi < 4; mi++)
#pragma unroll
                for (int nj = 0; nj < 4; nj++)
                    MMA_TF32(acc[mi][nj], a[mi], b[nj]);
        }
        __syncthreads();
    }

    // ---- epilogue
#pragma unroll
    for (int mi = 0; mi < 4; mi++) {
        const int r0 = m0 + wm * 64 + mi * 16 + g;
#pragma unroll
        for (int hf = 0; hf < 2; hf++) {
            const int m = r0 + hf * 8;
            if (m < cnt) {
                if (IS_UP) {
                    float* dstrow = g_act + (size_t)(base + m) * F;
#pragma unroll
                    for (int nj = 0; nj < 4; nj++) {
                        const int c = n0 + wn * 32 + nj * 8 + 2 * t;
                        const float v0 = acc[mi][nj][hf * 2];
                        const float v1 = acc[mi][nj][hf * 2 + 1];
                        float2 r;
                        r.x = to_tf32(v0 / (1.f + expf(-v0)));   // pre-rounded for down GEMM
                        r.y = to_tf32(v1 / (1.f + expf(-v1)));
                        *(float2*)(dstrow + c) = r;
                    }
                } else {
                    const int   tok = g_tok[e * NTOK + m];
                    const float wt  = g_wt [e * NTOK + m];
                    float* dstrow = out + (size_t)tok * H;
#pragma unroll
                    for (int nj = 0; nj < 4; nj++) {
                        const int c = n0 + wn * 32 + nj * 8 + 2 * t;
                        atomicAdd(dstrow + c,     acc[mi][nj][hf * 2]     * wt);
                        atomicAdd(dstrow + c + 1, acc[mi][nj][hf * 2 + 1] * wt);
                    }
                }
            }
        }
    }
}

// ---------------- launch ----------------
extern "C" void kernel_launch(void* const* d_in, const int* in_sizes, int n_in,
                              void* d_out, int out_size) {
    const float* x  = (const float*)d_in[0];
    const float* gw = (const float*)d_in[1];
    const float* w1 = (const float*)d_in[2];
    const float* w2 = (const float*)d_in[3];
    const int*   tk = (const int*)d_in[4];
    float* out = (float*)d_out;

    cudaMemsetAsync(out, 0, (size_t)out_size * sizeof(float));
    zero_counts_kernel<<<1, 32>>>();
    router_kernel<<<NTOK, 256>>>(x, gw, tk);
    offs_kernel<<<1, 32>>>();

    cvt_x_kernel<<<(NTOK * H) / 1024, 256>>>(x);

    dim3 gup(F / BN, NTOK / BM, E);
    mma_gemm_kernel<true,  H, F><<<gup, 128>>>(w1, nullptr);

    dim3 gdn(H / BN, NTOK / BM, E);
    mma_gemm_kernel<false, F, H><<<gdn, 128>>>(w2, out);
}

// round 10
// speedup vs baseline: 1.5492x; 1.4440x over previous
#include <cuda_runtime.h>
#include <math.h>
#include <stdint.h>

#define H    1024
#define F    2816
#define E    8
#define NTOK 2048
#define MAXK 2

#define BM 128
#define BN 128
#define BK 32

#define SMEM_FLOATS (2 * (BM * BK) + 2 * (BN * BK))   // 16384 floats
#define SMEM_BYTES  (SMEM_FLOATS * 4)                 // 65536

// ---------------- device scratch (static, no allocation) ----------------
__device__ int   g_count[E];
__device__ int   g_offs[E];
__device__ int   g_tok[E * NTOK];
__device__ float g_wt [E * NTOK];
__device__ float g_act[(size_t)MAXK * NTOK * F];       // tf32-rounded silu activations
__device__ float g_x32 [(size_t)NTOK * H];             // tf32-rounded x

// ---------------- helpers ----------------
__device__ __forceinline__ float to_tf32(float x) {
    float r; asm("cvt.rna.tf32.f32 %0, %1;" : "=f"(r) : "f"(x)); return r;
}
__device__ __forceinline__ uint32_t cvt_frag(float x) {
    float r; asm("cvt.rna.tf32.f32 %0, %1;" : "=f"(r) : "f"(x));
    return __float_as_uint(r);
}
__device__ __forceinline__ uint32_t smem_u32(const void* p) {
    uint32_t a;
    asm("{ .reg .u64 t; cvta.to.shared.u64 t, %1; cvt.u32.u64 %0, t; }" : "=r"(a) : "l"(p));
    return a;
}

#define CP_A16(dst, src, n) asm volatile("cp.async.cg.shared.global [%0], [%1], 16, %2;" :: "r"(dst), "l"(src), "r"(n))
#define CP_COMMIT()         asm volatile("cp.async.commit_group;" ::: "memory")
#define CP_WAIT1()          asm volatile("cp.async.wait_group 1;" ::: "memory")
#define CP_WAIT0()          asm volatile("cp.async.wait_group 0;" ::: "memory")

#define MMA_TF32(c, a, b)                                                        \
    asm volatile("mma.sync.aligned.m16n8k8.row.col.f32.tf32.tf32.f32 "           \
        "{%0,%1,%2,%3}, {%4,%5,%6,%7}, {%8,%9}, {%0,%1,%2,%3};"                  \
        : "+f"((c)[0]), "+f"((c)[1]), "+f"((c)[2]), "+f"((c)[3])                 \
        : "r"((a)[0]), "r"((a)[1]), "r"((a)[2]), "r"((a)[3]),                    \
          "r"((b)[0]), "r"((b)[1]))

// ---------------- tiny kernels ----------------
__global__ void zero_counts_kernel() { if (threadIdx.x < E) g_count[threadIdx.x] = 0; }

__global__ void offs_kernel() {
    if (threadIdx.x == 0) {
        int o = 0;
        for (int e = 0; e < E; e++) { g_offs[e] = o; o += g_count[e]; }
    }
}

__global__ __launch_bounds__(256) void cvt_x_kernel(const float* __restrict__ src) {
    const size_t i = (size_t)blockIdx.x * 256 + threadIdx.x;
    float4 v = ((const float4*)src)[i];
    v.x = to_tf32(v.x); v.y = to_tf32(v.y); v.z = to_tf32(v.z); v.w = to_tf32(v.w);
    ((float4*)g_x32)[i] = v;
}

// ---------------- router ----------------
__global__ __launch_bounds__(256) void router_kernel(const float* __restrict__ x,
                                                     const float* __restrict__ gw,
                                                     const int* __restrict__ topk_ptr) {
    const int token = blockIdx.x;
    const float* xr = x + (size_t)token * H;
    float p[E];
#pragma unroll
    for (int e = 0; e < E; e++) p[e] = 0.f;
    for (int h = threadIdx.x; h < H; h += blockDim.x) {
        const float xv = xr[h];
#pragma unroll
        for (int e = 0; e < E; e++) p[e] += xv * gw[e * H + h];
    }
#pragma unroll
    for (int e = 0; e < E; e++)
#pragma unroll
        for (int o = 16; o > 0; o >>= 1) p[e] += __shfl_xor_sync(0xffffffffu, p[e], o);

    __shared__ float sp[8][E];
    const int warp = threadIdx.x >> 5, lane = threadIdx.x & 31;
    if (lane == 0)
#pragma unroll
        for (int e = 0; e < E; e++) sp[warp][e] = p[e];
    __syncthreads();

    if (threadIdx.x == 0) {
        float lg[E];
#pragma unroll
        for (int e = 0; e < E; e++) {
            float s = 0.f;
            for (int w = 0; w < 8; w++) s += sp[w][e];
            lg[e] = s;
        }
        float mx = lg[0];
#pragma unroll
        for (int e = 1; e < E; e++) mx = fmaxf(mx, lg[e]);
        float pr[E], psum = 0.f;
#pragma unroll
        for (int e = 0; e < E; e++) { pr[e] = expf(lg[e] - mx); psum += pr[e]; }
#pragma unroll
        for (int e = 0; e < E; e++) pr[e] /= psum;

        int k = topk_ptr[0];
        if (k < 1) k = 1;
        if (k > MAXK) k = MAXK;

        bool used[E];
#pragma unroll
        for (int e = 0; e < E; e++) used[e] = false;
        int sel[MAXK]; float sw[MAXK]; float ssum = 0.f;
        for (int j = 0; j < k; j++) {
            int best = -1; float bv = -1.f;
            for (int e = 0; e < E; e++)
                if (!used[e] && pr[e] > bv) { bv = pr[e]; best = e; }
            used[best] = true; sel[j] = best; sw[j] = bv; ssum += bv;
        }
        const float inv = 1.f / ssum;
        for (int j = 0; j < k; j++) {
            const int ee = sel[j];
            const int pos = atomicAdd(&g_count[ee], 1);
            g_tok[ee * NTOK + pos] = token;
            g_wt [ee * NTOK + pos] = sw[j] * inv;
        }
    }
}

// ---------------- tf32 mma.sync grouped GEMM ----------------
// 128x128 tile, 256 threads, 8 warps (2M x 4N), warp tile 64x32.
// cp.async double-buffered; dynamic smem 64KB; 2 CTAs/SM via launch_bounds.
// A pre-rounded (g_x32 / g_act); B raw weights rounded on fragments.
template <bool IS_UP, int K, int NB>
__global__ __launch_bounds__(256, 2) void mma_gemm_kernel(const float* __restrict__ Bsrc,
                                                          float* __restrict__ out) {
    const int e   = blockIdx.z;
    const int cnt = g_count[e];
    const int m0  = blockIdx.y * BM;
    if (m0 >= cnt) return;
    const int n0   = blockIdx.x * BN;
    const int base = g_offs[e];

    extern __shared__ float dsm[];
    // layout: A stage0 | A stage1 | B stage0 | B stage1 (each BM*BK / BN*BK floats)
    float* sA = dsm;                       // [2][BM][BK]
    float* sB = dsm + 2 * BM * BK;         // [2][BN][BK]

    const int tid  = threadIdx.x;
    const int lane = tid & 31;
    const int warp = tid >> 5;
    const int wm   = warp & 1;       // 0..1
    const int wn   = warp >> 1;      // 0..3
    const int g    = lane >> 2;      // 0..7
    const int t    = lane & 3;       // 0..3

    const float* Asrc = IS_UP ? g_x32 : g_act;

    // staging: thread owns row tid>>1 of A and B, chunks (tid&1)*4 .. +3 (16B each)
    const int srow = tid >> 1;
    const int am = m0 + srow;
    const bool aval = am < cnt;
    const float* aptr;
    if (IS_UP) aptr = aval ? Asrc + (size_t)g_tok[e * NTOK + am] * K : Asrc;
    else       aptr = aval ? Asrc + (size_t)(base + am) * K : Asrc;
    const float* bptr = Bsrc + (size_t)e * NB * K + (size_t)(n0 + srow) * K;

    const uint32_t sA0 = smem_u32(sA);
    const uint32_t sB0 = smem_u32(sB);
    uint32_t dstA[4], dstB[4];
    int  chs[4];
#pragma unroll
    for (int j = 0; j < 4; j++) {
        const int ch = (tid & 1) * 4 + j;
        chs[j] = ch;
        const uint32_t off = (uint32_t)srow * (BK * 4) + (uint32_t)((ch ^ (srow & 7)) * 16);
        dstA[j] = sA0 + off;
        dstB[j] = sB0 + off;
    }
    const uint32_t abuf = BM * BK * 4;   // bytes per A stage
    const uint32_t bbuf = BN * BK * 4;
    const int asz = aval ? 16 : 0;

    float acc[4][4][4];
#pragma unroll
    for (int i = 0; i < 4; i++)
#pragma unroll
        for (int j = 0; j < 4; j++)
#pragma unroll
            for (int c = 0; c < 4; c++) acc[i][j][c] = 0.f;

    const int NS = K / BK;

    // prologue: stage slab 0 -> buf 0
#pragma unroll
    for (int j = 0; j < 4; j++) {
        CP_A16(dstA[j], aptr + chs[j] * 4, asz);
        CP_A16(dstB[j], bptr + chs[j] * 4, 16);
    }
    CP_COMMIT();

    for (int s = 0; s < NS; s++) {
        if (s + 1 < NS) {
            const uint32_t bo = ((s + 1) & 1);
            const float* as = aptr + (s + 1) * BK;
            const float* bs = bptr + (s + 1) * BK;
#pragma unroll
            for (int j = 0; j < 4; j++) {
                CP_A16(dstA[j] + bo * abuf, as + chs[j] * 4, asz);
                CP_A16(dstB[j] + bo * bbuf, bs + chs[j] * 4, 16);
            }
            CP_COMMIT();
            CP_WAIT1();
        } else {
            CP_WAIT0();
        }
        __syncthreads();

        const float* cA = sA + (s & 1) * (BM * BK);
        const float* cB = sB + (s & 1) * (BN * BK);
#pragma unroll
        for (int kk = 0; kk < 4; kk++) {
            uint32_t a[4][4], b[4][2];
#pragma unroll
            for (int mi = 0; mi < 4; mi++) {
                const int ar0 = wm * 64 + mi * 16 + g;
                const int i0 = ((2 * kk)     ^ (ar0 & 7)) * 4 + t;
                const int i1 = ((2 * kk + 1) ^ (ar0 & 7)) * 4 + t;
                a[mi][0] = __float_as_uint(cA[ ar0      * BK + i0]);
                a[mi][1] = __float_as_uint(cA[(ar0 + 8) * BK + i0]);
                a[mi][2] = __float_as_uint(cA[ ar0      * BK + i1]);
                a[mi][3] = __float_as_uint(cA[(ar0 + 8) * BK + i1]);
            }
#pragma unroll
            for (int nj = 0; nj < 4; nj++) {
                const int bn = wn * 32 + nj * 8 + g;
                const int i0 = ((2 * kk)     ^ (bn & 7)) * 4 + t;
                const int i1 = ((2 * kk + 1) ^ (bn & 7)) * 4 + t;
                b[nj][0] = cvt_frag(cB[bn * BK + i0]);
                b[nj][1] = cvt_frag(cB[bn * BK + i1]);
            }
#pragma unroll
            for (int mi = 0; mi < 4; mi++)
#pragma unroll
                for (int nj = 0; nj < 4; nj++)
                    MMA_TF32(acc[mi][nj], a[mi], b[nj]);
        }
        __syncthreads();
    }

    // ---- epilogue
#pragma unroll
    for (int mi = 0; mi < 4; mi++) {
        const int r0 = m0 + wm * 64 + mi * 16 + g;
#pragma unroll
        for (int hf = 0; hf < 2; hf++) {
            const int m = r0 + hf * 8;
            if (m < cnt) {
                if (IS_UP) {
                    float* dstrow = g_act + (size_t)(base + m) * F;
#pragma unroll
                    for (int nj = 0; nj < 4; nj++) {
                        const int c = n0 + wn * 32 + nj * 8 + 2 * t;
                        const float v0 = acc[mi][nj][hf * 2];
                        const float v1 = acc[mi][nj][hf * 2 + 1];
                        float2 r;
                        r.x = to_tf32(v0 / (1.f + expf(-v0)));
                        r.y = to_tf32(v1 / (1.f + expf(-v1)));
                        *(float2*)(dstrow + c) = r;
                    }
                } else {
                    const int   tok = g_tok[e * NTOK + m];
                    const float wt  = g_wt [e * NTOK + m];
                    float* dstrow = out + (size_t)tok * H;
#pragma unroll
                    for (int nj = 0; nj < 4; nj++) {
                        const int c = n0 + wn * 32 + nj * 8 + 2 * t;
                        atomicAdd(dstrow + c,     acc[mi][nj][hf * 2]     * wt);
                        atomicAdd(dstrow + c + 1, acc[mi][nj][hf * 2 + 1] * wt);
                    }
                }
            }
        }
    }
}

// ---------------- launch ----------------
extern "C" void kernel_launch(void* const* d_in, const int* in_sizes, int n_in,
                              void* d_out, int out_size) {
    const float* x  = (const float*)d_in[0];
    const float* gw = (const float*)d_in[1];
    const float* w1 = (const float*)d_in[2];
    const float* w2 = (const float*)d_in[3];
    const int*   tk = (const int*)d_in[4];
    float* out = (float*)d_out;

    // host-side attribute set (immediate, not a captured stream op; idempotent)
    cudaFuncSetAttribute(mma_gemm_kernel<true,  H, F>,
                         cudaFuncAttributeMaxDynamicSharedMemorySize, SMEM_BYTES);
    cudaFuncSetAttribute(mma_gemm_kernel<false, F, H>,
                         cudaFuncAttributeMaxDynamicSharedMemorySize, SMEM_BYTES);

    cudaMemsetAsync(out, 0, (size_t)out_size * sizeof(float));
    zero_counts_kernel<<<1, 32>>>();
    router_kernel<<<NTOK, 256>>>(x, gw, tk);
    offs_kernel<<<1, 32>>>();

    cvt_x_kernel<<<(NTOK * H) / 1024, 256>>>(x);

    dim3 gup(F / BN, NTOK / BM, E);
    mma_gemm_kernel<true,  H, F><<<gup, 256, SMEM_BYTES>>>(w1, nullptr);

    dim3 gdn(H / BN, NTOK / BM, E);
    mma_gemm_kernel<false, F, H><<<gdn, 256, SMEM_BYTES>>>(w2, out);
}

// round 13
// speedup vs baseline: 1.7427x; 1.1249x over previous
#include <cuda_runtime.h>
#include <math.h>
#include <stdint.h>

#define H    1024
#define F    2816
#define E    8
#define NTOK 2048
#define MAXK 2

#define BM 128
#define BN 128
#define BK 32
#define STAGES 3

#define SMEM_FLOATS (STAGES * (BM * BK + BN * BK))    // 24576 floats
#define SMEM_BYTES  (SMEM_FLOATS * 4)                 // 98304

// ---------------- device scratch (static, no allocation) ----------------
__device__ int   g_count[E];
__device__ int   g_offs[E];
__device__ int   g_tok[E * NTOK];
__device__ float g_wt [E * NTOK];
__device__ float g_act[(size_t)MAXK * NTOK * F];       // tf32-rounded silu activations
__device__ float g_x32 [(size_t)NTOK * H];             // tf32-rounded x

// ---------------- helpers ----------------
__device__ __forceinline__ float to_tf32(float x) {
    float r; asm("cvt.rna.tf32.f32 %0, %1;" : "=f"(r) : "f"(x)); return r;
}
__device__ __forceinline__ uint32_t cvt_frag(float x) {
    float r; asm("cvt.rna.tf32.f32 %0, %1;" : "=f"(r) : "f"(x));
    return __float_as_uint(r);
}
__device__ __forceinline__ uint32_t smem_u32(const void* p) {
    uint32_t a;
    asm("{ .reg .u64 t; cvta.to.shared.u64 t, %1; cvt.u32.u64 %0, t; }" : "=r"(a) : "l"(p));
    return a;
}

#define CP_A16(dst, src, n) asm volatile("cp.async.cg.shared.global [%0], [%1], 16, %2;" :: "r"(dst), "l"(src), "r"(n))
#define CP_COMMIT()         asm volatile("cp.async.commit_group;" ::: "memory")
#define CP_WAIT1()          asm volatile("cp.async.wait_group 1;" ::: "memory")

#define MMA_TF32(c, a, b)                                                        \
    asm volatile("mma.sync.aligned.m16n8k8.row.col.f32.tf32.tf32.f32 "           \
        "{%0,%1,%2,%3}, {%4,%5,%6,%7}, {%8,%9}, {%0,%1,%2,%3};"                  \
        : "+f"((c)[0]), "+f"((c)[1]), "+f"((c)[2]), "+f"((c)[3])                 \
        : "r"((a)[0]), "r"((a)[1]), "r"((a)[2]), "r"((a)[3]),                    \
          "r"((b)[0]), "r"((b)[1]))

// ---------------- tiny kernels ----------------
__global__ void zero_counts_kernel() { if (threadIdx.x < E) g_count[threadIdx.x] = 0; }

__global__ void offs_kernel() {
    if (threadIdx.x == 0) {
        int o = 0;
        for (int e = 0; e < E; e++) { g_offs[e] = o; o += g_count[e]; }
    }
}

__global__ __launch_bounds__(256) void cvt_x_kernel(const float* __restrict__ src) {
    const size_t i = (size_t)blockIdx.x * 256 + threadIdx.x;
    float4 v = ((const float4*)src)[i];
    v.x = to_tf32(v.x); v.y = to_tf32(v.y); v.z = to_tf32(v.z); v.w = to_tf32(v.w);
    ((float4*)g_x32)[i] = v;
}

// ---------------- router ----------------
__global__ __launch_bounds__(256) void router_kernel(const float* __restrict__ x,
                                                     const float* __restrict__ gw,
                                                     const int* __restrict__ topk_ptr) {
    const int token = blockIdx.x;
    const float* xr = x + (size_t)token * H;
    float p[E];
#pragma unroll
    for (int e = 0; e < E; e++) p[e] = 0.f;
    for (int h = threadIdx.x; h < H; h += blockDim.x) {
        const float xv = xr[h];
#pragma unroll
        for (int e = 0; e < E; e++) p[e] += xv * gw[e * H + h];
    }
#pragma unroll
    for (int e = 0; e < E; e++)
#pragma unroll
        for (int o = 16; o > 0; o >>= 1) p[e] += __shfl_xor_sync(0xffffffffu, p[e], o);

    __shared__ float sp[8][E];
    const int warp = threadIdx.x >> 5, lane = threadIdx.x & 31;
    if (lane == 0)
#pragma unroll
        for (int e = 0; e < E; e++) sp[warp][e] = p[e];
    __syncthreads();

    if (threadIdx.x == 0) {
        float lg[E];
#pragma unroll
        for (int e = 0; e < E; e++) {
            float s = 0.f;
            for (int w = 0; w < 8; w++) s += sp[w][e];
            lg[e] = s;
        }
        float mx = lg[0];
#pragma unroll
        for (int e = 1; e < E; e++) mx = fmaxf(mx, lg[e]);
        float pr[E], psum = 0.f;
#pragma unroll
        for (int e = 0; e < E; e++) { pr[e] = expf(lg[e] - mx); psum += pr[e]; }
#pragma unroll
        for (int e = 0; e < E; e++) pr[e] /= psum;

        int k = topk_ptr[0];
        if (k < 1) k = 1;
        if (k > MAXK) k = MAXK;

        bool used[E];
#pragma unroll
        for (int e = 0; e < E; e++) used[e] = false;
        int sel[MAXK]; float sw[MAXK]; float ssum = 0.f;
        for (int j = 0; j < k; j++) {
            int best = -1; float bv = -1.f;
            for (int e = 0; e < E; e++)
                if (!used[e] && pr[e] > bv) { bv = pr[e]; best = e; }
            used[best] = true; sel[j] = best; sw[j] = bv; ssum += bv;
        }
        const float inv = 1.f / ssum;
        for (int j = 0; j < k; j++) {
            const int ee = sel[j];
            const int pos = atomicAdd(&g_count[ee], 1);
            g_tok[ee * NTOK + pos] = token;
            g_wt [ee * NTOK + pos] = sw[j] * inv;
        }
    }
}

// ---------------- tf32 mma.sync grouped GEMM, 3-stage cp.async pipeline ----------------
// 128x128 tile, 256 threads, 8 warps (2M x 4N), warp tile 64x32.
// One __syncthreads per slab (multistage ordering: wait -> sync -> compute -> issue).
template <bool IS_UP, int K, int NB>
__global__ __launch_bounds__(256, 2) void mma_gemm_kernel(const float* __restrict__ Bsrc,
                                                          float* __restrict__ out) {
    const int e   = blockIdx.z;
    const int cnt = g_count[e];
    const int m0  = blockIdx.y * BM;
    if (m0 >= cnt) return;
    const int n0   = blockIdx.x * BN;
    const int base = g_offs[e];

    extern __shared__ float dsm[];
    float* sA = dsm;                           // [STAGES][BM][BK]
    float* sB = dsm + STAGES * BM * BK;        // [STAGES][BN][BK]

    const int tid  = threadIdx.x;
    const int lane = tid & 31;
    const int warp = tid >> 5;
    const int wm   = warp & 1;       // 0..1
    const int wn   = warp >> 1;      // 0..3
    const int g    = lane >> 2;      // 0..7
    const int t    = lane & 3;       // 0..3

    const float* Asrc = IS_UP ? g_x32 : g_act;

    // staging: thread owns row tid>>1 of A and B, chunks (tid&1)*4 .. +3 (16B each)
    const int srow = tid >> 1;
    const int am = m0 + srow;
    const bool aval = am < cnt;
    const float* aptr;
    if (IS_UP) aptr = aval ? Asrc + (size_t)g_tok[e * NTOK + am] * K : Asrc;
    else       aptr = aval ? Asrc + (size_t)(base + am) * K : Asrc;
    const float* bptr = Bsrc + (size_t)e * NB * K + (size_t)(n0 + srow) * K;

    const uint32_t sA0 = smem_u32(sA);
    const uint32_t sB0 = smem_u32(sB);
    uint32_t dstA[4], dstB[4];
    int  chs[4];
#pragma unroll
    for (int j = 0; j < 4; j++) {
        const int ch = (tid & 1) * 4 + j;
        chs[j] = ch;
        const uint32_t off = (uint32_t)srow * (BK * 4) + (uint32_t)((ch ^ (srow & 7)) * 16);
        dstA[j] = sA0 + off;
        dstB[j] = sB0 + off;
    }
    const uint32_t abuf = BM * BK * 4;   // bytes per A stage
    const uint32_t bbuf = BN * BK * 4;
    const int asz = aval ? 16 : 0;

    float acc[4][4][4];
#pragma unroll
    for (int i = 0; i < 4; i++)
#pragma unroll
        for (int j = 0; j < 4; j++)
#pragma unroll
            for (int c = 0; c < 4; c++) acc[i][j][c] = 0.f;

    const int NS = K / BK;

    // prologue: stage slabs 0 and 1
#pragma unroll
    for (int st = 0; st < 2; st++) {
        const float* as = aptr + st * BK;
        const float* bs = bptr + st * BK;
#pragma unroll
        for (int j = 0; j < 4; j++) {
            CP_A16(dstA[j] + st * abuf, as + chs[j] * 4, asz);
            CP_A16(dstB[j] + st * bbuf, bs + chs[j] * 4, 16);
        }
        CP_COMMIT();
    }

    int cstage = 0;                         // buffer index of slab s
    for (int s = 0; s < NS; s++) {
        CP_WAIT1();                          // slab s complete (s+1 may pend)
        __syncthreads();                     // all copies visible to all warps

        const float* cA = sA + cstage * (BM * BK);
        const float* cB = sB + cstage * (BN * BK);
#pragma unroll
        for (int kk = 0; kk < 4; kk++) {
            uint32_t a[4][4], b[4][2];
#pragma unroll
            for (int mi = 0; mi < 4; mi++) {
                const int ar0 = wm * 64 + mi * 16 + g;
                const int i0 = ((2 * kk)     ^ (ar0 & 7)) * 4 + t;
                const int i1 = ((2 * kk + 1) ^ (ar0 & 7)) * 4 + t;
                a[mi][0] = __float_as_uint(cA[ ar0      * BK + i0]);
                a[mi][1] = __float_as_uint(cA[(ar0 + 8) * BK + i0]);
                a[mi][2] = __float_as_uint(cA[ ar0      * BK + i1]);
                a[mi][3] = __float_as_uint(cA[(ar0 + 8) * BK + i1]);
            }
#pragma unroll
            for (int nj = 0; nj < 4; nj++) {
                const int bn = wn * 32 + nj * 8 + g;
                const int i0 = ((2 * kk)     ^ (bn & 7)) * 4 + t;
                const int i1 = ((2 * kk + 1) ^ (bn & 7)) * 4 + t;
                b[nj][0] = cvt_frag(cB[bn * BK + i0]);
                b[nj][1] = cvt_frag(cB[bn * BK + i1]);
            }
#pragma unroll
            for (int mi = 0; mi < 4; mi++)
#pragma unroll
                for (int nj = 0; nj < 4; nj++)
                    MMA_TF32(acc[mi][nj], a[mi], b[nj]);
        }

        // issue slab s+2 into the buffer freed at iteration s-1 (safe: all warps
        // passed this iteration's sync, hence finished computing s-1)
        if (s + 2 < NS) {
            const int wstage = (cstage + 2 >= STAGES) ? cstage + 2 - STAGES : cstage + 2;
            const float* as = aptr + (s + 2) * BK;
            const float* bs = bptr + (s + 2) * BK;
#pragma unroll
            for (int j = 0; j < 4; j++) {
                CP_A16(dstA[j] + wstage * abuf, as + chs[j] * 4, asz);
                CP_A16(dstB[j] + wstage * bbuf, bs + chs[j] * 4, 16);
            }
        }
        CP_COMMIT();                         // always commit (keeps wait count invariant)

        cstage = (cstage + 1 == STAGES) ? 0 : cstage + 1;
    }

    // ---- epilogue
#pragma unroll
    for (int mi = 0; mi < 4; mi++) {
        const int r0 = m0 + wm * 64 + mi * 16 + g;
#pragma unroll
        for (int hf = 0; hf < 2; hf++) {
            const int m = r0 + hf * 8;
            if (m < cnt) {
                if (IS_UP) {
                    float* dstrow = g_act + (size_t)(base + m) * F;
#pragma unroll
                    for (int nj = 0; nj < 4; nj++) {
                        const int c = n0 + wn * 32 + nj * 8 + 2 * t;
                        const float v0 = acc[mi][nj][hf * 2];
                        const float v1 = acc[mi][nj][hf * 2 + 1];
                        float2 r;
                        r.x = to_tf32(v0 / (1.f + expf(-v0)));
                        r.y = to_tf32(v1 / (1.f + expf(-v1)));
                        *(float2*)(dstrow + c) = r;
                    }
                } else {
                    const int   tok = g_tok[e * NTOK + m];
                    const float wt  = g_wt [e * NTOK + m];
                    float* dstrow = out + (size_t)tok * H;
#pragma unroll
                    for (int nj = 0; nj < 4; nj++) {
                        const int c = n0 + wn * 32 + nj * 8 + 2 * t;
                        atomicAdd(dstrow + c,     acc[mi][nj][hf * 2]     * wt);
                        atomicAdd(dstrow + c + 1, acc[mi][nj][hf * 2 + 1] * wt);
                    }
                }
            }
        }
    }
}

// ---------------- launch ----------------
extern "C" void kernel_launch(void* const* d_in, const int* in_sizes, int n_in,
                              void* d_out, int out_size) {
    const float* x  = (const float*)d_in[0];
    const float* gw = (const float*)d_in[1];
    const float* w1 = (const float*)d_in[2];
    const float* w2 = (const float*)d_in[3];
    const int*   tk = (const int*)d_in[4];
    float* out = (float*)d_out;

    cudaFuncSetAttribute(mma_gemm_kernel<true,  H, F>,
                         cudaFuncAttributeMaxDynamicSharedMemorySize, SMEM_BYTES);
    cudaFuncSetAttribute(mma_gemm_kernel<false, F, H>,
                         cudaFuncAttributeMaxDynamicSharedMemorySize, SMEM_BYTES);

    cudaMemsetAsync(out, 0, (size_t)out_size * sizeof(float));
    zero_counts_kernel<<<1, 32>>>();
    router_kernel<<<NTOK, 256>>>(x, gw, tk);
    offs_kernel<<<1, 32>>>();

    cvt_x_kernel<<<(NTOK * H) / 1024, 256>>>(x);

    dim3 gup(F / BN, NTOK / BM, E);
    mma_gemm_kernel<true,  H, F><<<gup, 256, SMEM_BYTES>>>(w1, nullptr);

    dim3 gdn(H / BN, NTOK / BM, E);
    mma_gemm_kernel<false, F, H><<<gdn, 256, SMEM_BYTES>>>(w2, out);
}